// round 1
// baseline (speedup 1.0000x reference)
#include <cuda_runtime.h>
#include <cooperative_groups.h>

namespace cg = cooperative_groups;

#define TT 1200
#define BB 256
#define HH 128
#define II 16
#define CSIZE 4
#define BC 8          // batch per cluster
#define NTHREADS 256
#define NCTAS 128     // 32 clusters * 4

// Dynamic shared layout: all weights resident for the whole run.
struct Smem {
    float Wih0[II][HH];    // [k][lr], lr = jj*4 + gate
    float Whh0[HH][HH];
    float Wih1[HH][HH];
    float Whh1[HH][HH];
    float b0[HH];          // b_ih0 + b_hh0, permuted to lr
    float b1[HH];
    float wlin[HH];        // plain h-index order
    float h0buf[2][HH][BC];  // [buf][h_index][b], full h replicated per CTA
    float h1buf[2][HH][BC];
    float xs[II][BC];
    float red[32][36];     // cross-warp-half partial sums, padded rows
    float blin;
};

__device__ __forceinline__ float sig_f(float x) {
    return __fdividef(1.0f, 1.0f + __expf(-x));
}
__device__ __forceinline__ float tanh_f(float x) {
    return __fdividef(2.0f, 1.0f + __expf(-2.0f * x)) - 1.0f;
}

// Accumulate acc[g][b] += W[k][lroff+g] * src[k][b] over this thread's k-slice.
template <int KT>
__device__ __forceinline__ void accum(float acc[4][8],
                                      const float* __restrict__ W,
                                      const float* __restrict__ src,
                                      int ks, int lroff) {
    constexpr int KPT = KT / 8;
    const float* Wp = W + ks * KPT * HH + lroff;
    const float* Sp = src + ks * KPT * BC;
#pragma unroll
    for (int k = 0; k < KPT; k++) {
        float4 wv = *(const float4*)(Wp + k * HH);
        float4 s0 = *(const float4*)(Sp + k * BC);
        float4 s1 = *(const float4*)(Sp + k * BC + 4);
        float s[8] = {s0.x, s0.y, s0.z, s0.w, s1.x, s1.y, s1.z, s1.w};
#pragma unroll
        for (int b = 0; b < 8; b++) {
            acc[0][b] = fmaf(wv.x, s[b], acc[0][b]);
            acc[1][b] = fmaf(wv.y, s[b], acc[1][b]);
            acc[2][b] = fmaf(wv.z, s[b], acc[2][b]);
            acc[3][b] = fmaf(wv.w, s[b], acc[3][b]);
        }
    }
}

// Butterfly-reduce the 4 in-warp k-slices, combine warp halves through smem,
// apply gates, update c, and push h to all 4 cluster CTAs via DSMEM.
__device__ __forceinline__ void reduce_update_store(
    float acc[4][8], float* __restrict__ red, const float* __restrict__ bias,
    float cpair[2], float (*hdst)[BC], int q, int warp, int lane,
    cg::cluster_group& cluster) {
#pragma unroll
    for (int g = 0; g < 4; g++)
#pragma unroll
        for (int b = 0; b < 8; b++) {
            acc[g][b] += __shfl_xor_sync(0xffffffffu, acc[g][b], 8);
            acc[g][b] += __shfl_xor_sync(0xffffffffu, acc[g][b], 16);
        }
    int jj = (warp & 3) * 8 + (lane & 7);
    if (warp >= 4 && lane < 8) {
        float* r = red + jj * 36;
#pragma unroll
        for (int g = 0; g < 4; g++) {
            *(float4*)(r + g * 8)     = make_float4(acc[g][0], acc[g][1], acc[g][2], acc[g][3]);
            *(float4*)(r + g * 8 + 4) = make_float4(acc[g][4], acc[g][5], acc[g][6], acc[g][7]);
        }
    }
    __syncthreads();
    if (warp < 4) {
        const float* r = red + jj * 36;
        int bp = (lane >> 3) * 2;
        float hv[2];
#pragma unroll
        for (int u = 0; u < 2; u++) {
            int b = bp + u;
            float iv = sig_f (acc[0][b] + r[0 * 8 + b] + bias[jj * 4 + 0]);
            float fv = sig_f (acc[1][b] + r[1 * 8 + b] + bias[jj * 4 + 1]);
            float gv = tanh_f(acc[2][b] + r[2 * 8 + b] + bias[jj * 4 + 2]);
            float ov = sig_f (acc[3][b] + r[3 * 8 + b] + bias[jj * 4 + 3]);
            float c = fv * cpair[u] + iv * gv;
            cpair[u] = c;
            hv[u] = ov * tanh_f(c);
        }
        float2 h2 = make_float2(hv[0], hv[1]);
        float* lp = &hdst[q * 32 + jj][bp];
#pragma unroll
        for (int r2 = 0; r2 < CSIZE; r2++) {
            float* dst = cluster.map_shared_rank(lp, r2);
            *(float2*)dst = h2;
        }
    }
}

__global__ void __cluster_dims__(CSIZE, 1, 1) __launch_bounds__(NTHREADS, 1)
lstm_kernel(const float* __restrict__ x,
            const float* __restrict__ Wih0, const float* __restrict__ Whh0,
            const float* __restrict__ bih0, const float* __restrict__ bhh0,
            const float* __restrict__ Wih1, const float* __restrict__ Whh1,
            const float* __restrict__ bih1, const float* __restrict__ bhh1,
            const float* __restrict__ Wlin, const float* __restrict__ blin,
            float* __restrict__ out) {
    extern __shared__ char smem_bytes[];
    Smem* sm = (Smem*)smem_bytes;
    cg::cluster_group cluster = cg::this_cluster();
    const int q = cluster.block_rank();           // 0..3 -> h-indices [q*32, q*32+32)
    const int tid = threadIdx.x;
    const int warp = tid >> 5, lane = tid & 31;
    const int cid = blockIdx.x / CSIZE;
    const int bbase = cid * BC;

    // ---- Load this CTA's weight slice (one-time, L2-served) ----
    for (int idx = tid; idx < HH * HH; idx += NTHREADS) {
        int k = idx >> 7, lr = idx & 127;
        int g = lr & 3, jj = lr >> 2;
        int grow = g * HH + q * 32 + jj;          // global gate row in [0,512)
        sm->Whh0[k][lr] = Whh0[grow * HH + k];
        sm->Wih1[k][lr] = Wih1[grow * HH + k];
        sm->Whh1[k][lr] = Whh1[grow * HH + k];
        if (k < II) sm->Wih0[k][lr] = Wih0[grow * II + k];
    }
    for (int lr = tid; lr < HH; lr += NTHREADS) {
        int g = lr & 3, jj = lr >> 2;
        int grow = g * HH + q * 32 + jj;
        sm->b0[lr] = bih0[grow] + bhh0[grow];
        sm->b1[lr] = bih1[grow] + bhh1[grow];
        sm->wlin[lr] = Wlin[lr];                  // plain index, no permutation
    }
    if (tid == 0) sm->blin = blin[0];
    for (int i = tid; i < 2 * HH * BC; i += NTHREADS) {
        ((float*)sm->h0buf)[i] = 0.0f;
        ((float*)sm->h1buf)[i] = 0.0f;
    }
    __syncthreads();
    cluster.sync();   // peers may write our h buffers from step 0 on

    float c0[2] = {0.0f, 0.0f}, c1[2] = {0.0f, 0.0f};
    const int lroff = ((warp & 3) * 8 + (lane & 7)) * 4;   // 4 contiguous lr rows
    const int ks = (warp >> 2) * 4 + (lane >> 3);          // k-slice 0..7

    for (int t = 0; t < TT; t++) {
        const int cur = t & 1, nxt = cur ^ 1;

        // stage x[:, t, :] for our batch slice
        if (tid < II * BC) {
            int b = tid >> 4, k = tid & 15;
            sm->xs[k][b] = x[((size_t)(bbase + b) * TT + t) * II + k];
        }
        __syncthreads();

        // ---- Layer 0 ----
        float acc[4][8];
#pragma unroll
        for (int g = 0; g < 4; g++)
#pragma unroll
            for (int b = 0; b < 8; b++) acc[g][b] = 0.0f;
        accum<II>(acc, &sm->Wih0[0][0], &sm->xs[0][0], ks, lroff);
        accum<HH>(acc, &sm->Whh0[0][0], &sm->h0buf[cur][0][0], ks, lroff);
        reduce_update_store(acc, &sm->red[0][0], sm->b0, c0, sm->h0buf[nxt],
                            q, warp, lane, cluster);
        cluster.sync();

        // ---- Layer 1 (consumes layer-0 h of the same step) ----
#pragma unroll
        for (int g = 0; g < 4; g++)
#pragma unroll
            for (int b = 0; b < 8; b++) acc[g][b] = 0.0f;
        accum<HH>(acc, &sm->Wih1[0][0], &sm->h0buf[nxt][0][0], ks, lroff);
        accum<HH>(acc, &sm->Whh1[0][0], &sm->h1buf[cur][0][0], ks, lroff);
        reduce_update_store(acc, &sm->red[0][0], sm->b1, c1, sm->h1buf[nxt],
                            q, warp, lane, cluster);
        cluster.sync();

        // ---- Fused ReLU + linear head (warp 7; others run ahead to t+1) ----
        if (warp == 7) {
            int b = lane & 7, kq = lane >> 3;
            float p = 0.0f;
#pragma unroll
            for (int i = 0; i < 32; i++) {
                int k = kq * 32 + i;
                float h = fmaxf(sm->h1buf[nxt][k][b], 0.0f);
                p = fmaf(h, sm->wlin[k], p);
            }
            p += __shfl_xor_sync(0xffffffffu, p, 8);
            p += __shfl_xor_sync(0xffffffffu, p, 16);
            if (lane < 8)
                out[(size_t)(bbase + b) * TT + t] = p + sm->blin;
        }
    }
}

extern "C" void kernel_launch(void* const* d_in, const int* in_sizes, int n_in,
                              void* d_out, int out_size) {
    const float* x    = (const float*)d_in[0];
    const float* Wih0 = (const float*)d_in[1];
    const float* Whh0 = (const float*)d_in[2];
    const float* bih0 = (const float*)d_in[3];
    const float* bhh0 = (const float*)d_in[4];
    const float* Wih1 = (const float*)d_in[5];
    const float* Whh1 = (const float*)d_in[6];
    const float* bih1 = (const float*)d_in[7];
    const float* bhh1 = (const float*)d_in[8];
    const float* Wlin = (const float*)d_in[9];
    const float* blin = (const float*)d_in[10];
    float* out = (float*)d_out;

    size_t smem = sizeof(Smem);
    cudaFuncSetAttribute(lstm_kernel, cudaFuncAttributeMaxDynamicSharedMemorySize,
                         (int)smem);
    lstm_kernel<<<NCTAS, NTHREADS, smem>>>(x, Wih0, Whh0, bih0, bhh0,
                                           Wih1, Whh1, bih1, bhh1,
                                           Wlin, blin, out);
}